// round 5
// baseline (speedup 1.0000x reference)
#include <cuda_runtime.h>
#include <cuda_bf16.h>
#include <stdint.h>
#include <math.h>

#define NR 8192
#define DD 512

// ---------------- scratch (__device__ globals; no allocs allowed) ----------------
__device__ __align__(128) __nv_bfloat16 g_xhi[(size_t)NR * DD];
__device__ __align__(128) __nv_bfloat16 g_xlo[(size_t)NR * DD];
__device__ __align__(128) __nv_bfloat16 g_wth[3][(size_t)DD * DD];   // W^T hi
__device__ __align__(128) __nv_bfloat16 g_wtl[3][(size_t)DD * DD];   // W^T lo
__device__ __align__(128) __nv_bfloat16 g_qhi[(size_t)NR * DD];
__device__ __align__(128) __nv_bfloat16 g_qlo[(size_t)NR * DD];
__device__ __align__(128) __nv_bfloat16 g_khi[(size_t)NR * DD];
__device__ __align__(128) __nv_bfloat16 g_klo[(size_t)NR * DD];
__device__ __align__(128) __nv_bfloat16 g_vt [(size_t)DD * NR];      // v^T only
__device__ __align__(128) __nv_bfloat16 g_E  [(size_t)NR * NR];      // 128 MB
__device__ float g_rowsum[NR];

// ---------------- helpers (arch-generic PTX: ldmatrix + mma.sync + cp.async) ---------
__device__ __forceinline__ uint32_t smem_u32(const void* p) {
    uint32_t a;
    asm("{ .reg .u64 t; cvta.to.shared.u64 t, %1; cvt.u32.u64 %0, t; }" : "=r"(a) : "l"(p));
    return a;
}
__device__ __forceinline__ void ldsm4(uint32_t r[4], uint32_t a) {
    asm volatile("ldmatrix.sync.aligned.m8n8.x4.shared.b16 {%0,%1,%2,%3}, [%4];"
                 : "=r"(r[0]), "=r"(r[1]), "=r"(r[2]), "=r"(r[3]) : "r"(a));
}
__device__ __forceinline__ void mma16816(float d[4], const uint32_t a[4], const uint32_t b[2]) {
    asm volatile("mma.sync.aligned.m16n8k16.row.col.f32.bf16.bf16.f32 "
                 "{%0,%1,%2,%3}, {%4,%5,%6,%7}, {%8,%9}, {%0,%1,%2,%3};"
                 : "+f"(d[0]), "+f"(d[1]), "+f"(d[2]), "+f"(d[3])
                 : "r"(a[0]), "r"(a[1]), "r"(a[2]), "r"(a[3]), "r"(b[0]), "r"(b[1]));
}
__device__ __forceinline__ void cp16(uint32_t saddr, const void* gaddr) {
    asm volatile("cp.async.cg.shared.global [%0], [%1], 16;" :: "r"(saddr), "l"(gaddr));
}
#define CP_COMMIT() asm volatile("cp.async.commit_group;" ::: "memory")
#define CP_WAIT1()  asm volatile("cp.async.wait_group 1;" ::: "memory")

__device__ __forceinline__ float exp2_poly(float t) {
    float fi = rintf(t);
    float f = t - fi;
    float p = 0.00015403530393381606f;
    p = fmaf(p, f, 0.0013333558146428443f);
    p = fmaf(p, f, 0.009618129107628477f);
    p = fmaf(p, f, 0.05550410866482158f);
    p = fmaf(p, f, 0.2402265069591007f);
    p = fmaf(p, f, 0.6931471805599453f);
    p = fmaf(p, f, 1.0f);
    return __int_as_float(((int)fi + 127) << 23) * p;
}

// ---------------- prep kernels ----------------
__global__ void split_x_k(const float4* __restrict__ x) {
    size_t i = (size_t)blockIdx.x * 256 + threadIdx.x;
    if (i < NR) g_rowsum[i] = 0.0f;                 // fused rowsum zeroing
    float4 v = x[i];
    __nv_bfloat16 hx = __float2bfloat16(v.x), hy = __float2bfloat16(v.y);
    __nv_bfloat16 hz = __float2bfloat16(v.z), hw = __float2bfloat16(v.w);
    __nv_bfloat162* H = (__nv_bfloat162*)g_xhi;
    __nv_bfloat162* L = (__nv_bfloat162*)g_xlo;
    H[2 * i]     = __halves2bfloat162(hx, hy);
    H[2 * i + 1] = __halves2bfloat162(hz, hw);
    L[2 * i]     = __halves2bfloat162(__float2bfloat16(v.x - __bfloat162float(hx)),
                                      __float2bfloat16(v.y - __bfloat162float(hy)));
    L[2 * i + 1] = __halves2bfloat162(__float2bfloat16(v.z - __bfloat162float(hz)),
                                      __float2bfloat16(v.w - __bfloat162float(hw)));
}

__global__ void trans_split_w_k(const float* __restrict__ W0, const float* __restrict__ W1,
                                const float* __restrict__ W2) {
    __shared__ float t[32][33];
    const float* W = (blockIdx.z == 0) ? W0 : (blockIdx.z == 1) ? W1 : W2;
    __nv_bfloat16* Th = g_wth[blockIdx.z];
    __nv_bfloat16* Tl = g_wtl[blockIdx.z];
    int tx = threadIdx.x, ty = threadIdx.y;
    int xi = blockIdx.x * 32 + tx, yi = blockIdx.y * 32 + ty;
    #pragma unroll
    for (int i = 0; i < 32; i += 8) t[ty + i][tx] = W[(size_t)(yi + i) * DD + xi];
    __syncthreads();
    int xo = blockIdx.y * 32 + tx, yo = blockIdx.x * 32 + ty;
    #pragma unroll
    for (int i = 0; i < 32; i += 8) {
        float v = t[tx][ty + i];
        __nv_bfloat16 h = __float2bfloat16(v);
        Th[(size_t)(yo + i) * DD + xo] = h;
        Tl[(size_t)(yo + i) * DD + xo] = __float2bfloat16(v - __bfloat162float(h));
    }
}

// ============ mma.sync GEMM: D[M,Ncols] = A[M,K] x B[Ncols,K]^T, bf16, fp32 accum ========
// NOP=2: acc = Ahi*Bhi + Alo*Bhi + Ahi*Blo   NOP=1: acc = A*B
// EPI 0: abs -> split (Chi, Clo)   EPI 1: abs -> bf16 TRANSPOSED scatter into Chi[N,?]
// EPI 2: exp2(acc*scale) -> bf16 Chi + rowsum atomics   EPI 3: acc/rowsum -> f32 Cf
// Block 128x128, BK=32, 8 warps (2m x 4n), warp 64x32 (4x4 m16n8k16).
// cp.async 3-stage pipeline, ONE barrier per chunk; smem 64B rows,
// swizzle: unit' = unit ^ ((row>>1)&3).
template<int NOP, int EPI>
__global__ __launch_bounds__(256, 2)
void mma_gemm(const __nv_bfloat16* __restrict__ Ahi, const __nv_bfloat16* __restrict__ Alo,
              const __nv_bfloat16* __restrict__ Bhi, const __nv_bfloat16* __restrict__ Blo,
              int Ncols, int K,
              __nv_bfloat16* __restrict__ Chi, __nv_bfloat16* __restrict__ Clo,
              float* __restrict__ Cf, float* __restrict__ rsum, float scale)
{
    constexpr int NT = 2 * NOP;                 // tiles per stage
    constexpr int NS = 3;                        // pipeline stages
    constexpr uint32_t STAGE = (uint32_t)NT * 8192u;
    extern __shared__ char dyn[];
    __shared__ float red[128][4];

    const int tid = threadIdx.x;
    const int lane = tid & 31, wid = tid >> 5;
    const int wm = wid & 1, wn = wid >> 1;
    const int m0 = blockIdx.y * 128, n0 = blockIdx.x * 128;
    const uint32_t sbase = smem_u32(dyn);

    const __nv_bfloat16* gsrc[NT];
    int rb[NT];
    if (NOP == 2) {
        gsrc[0] = Ahi; rb[0] = m0;
        gsrc[1] = Alo; rb[1] = m0;
        gsrc[2] = Bhi; rb[2] = n0;
        gsrc[3] = Blo; rb[3] = n0;
    } else {
        gsrc[0] = Ahi; rb[0] = m0;
        gsrc[1] = Bhi; rb[1] = n0;
    }

    const int su = tid & 3;
    const int sr0 = tid >> 2, sr1 = sr0 + 64;
    const uint32_t soff0 = sr0 * 64 + ((su ^ ((sr0 >> 1) & 3)) << 4);
    const uint32_t soff1 = sr1 * 64 + ((su ^ ((sr1 >> 1) & 3)) << 4);

    uint32_t offA[4][2], offB[2][2];
    {
        const int ra = lane & 15, ua = lane >> 4;
        #pragma unroll
        for (int mi = 0; mi < 4; mi++)
            #pragma unroll
            for (int ks = 0; ks < 2; ks++) {
                int r = wm * 64 + mi * 16 + ra;
                int u = ks * 2 + ua;
                offA[mi][ks] = r * 64 + ((u ^ ((r >> 1) & 3)) << 4);
            }
        const int rbv = ((lane >> 4) << 3) + (lane & 7), ub = (lane >> 3) & 1;
        #pragma unroll
        for (int np = 0; np < 2; np++)
            #pragma unroll
            for (int ks = 0; ks < 2; ks++) {
                int r = wn * 32 + np * 16 + rbv;
                int u = ks * 2 + ub;
                offB[np][ks] = r * 64 + ((u ^ ((r >> 1) & 3)) << 4);
            }
    }

    float acc[4][4][4];
    #pragma unroll
    for (int a = 0; a < 4; a++)
        #pragma unroll
        for (int b = 0; b < 4; b++)
            #pragma unroll
            for (int c = 0; c < 4; c++) acc[a][b][c] = 0.0f;

    const int nkt = K >> 5;

    // prologue: stage chunks 0, 1
    #pragma unroll
    for (int s = 0; s < NS - 1; s++) {
        const int kc = s * 32 + su * 8;
        const uint32_t db = sbase + (uint32_t)s * STAGE;
        #pragma unroll
        for (int t = 0; t < NT; t++) {
            cp16(db + t * 8192u + soff0, gsrc[t] + (size_t)(rb[t] + sr0) * K + kc);
            cp16(db + t * 8192u + soff1, gsrc[t] + (size_t)(rb[t] + sr1) * K + kc);
        }
        CP_COMMIT();
    }

    int stage = 0;
    for (int kt = 0; kt < nkt; kt++) {
        CP_WAIT1();              // chunk kt resident (<=1 group in flight after)
        __syncthreads();         // single barrier: also frees buffer of kt-1 for issue below

        const uint32_t bb = sbase + (uint32_t)stage * STAGE;
        #pragma unroll
        for (int ks = 0; ks < 2; ks++) {
            uint32_t ah[4][4];
            #pragma unroll
            for (int mi = 0; mi < 4; mi++) ldsm4(ah[mi], bb + offA[mi][ks]);
            uint32_t bh[2][4];
            constexpr uint32_t TBH = (NOP == 2) ? 2u * 8192u : 1u * 8192u;
            #pragma unroll
            for (int np = 0; np < 2; np++) ldsm4(bh[np], bb + TBH + offB[np][ks]);
            #pragma unroll
            for (int mi = 0; mi < 4; mi++)
                #pragma unroll
                for (int ni = 0; ni < 4; ni++)
                    mma16816(acc[mi][ni], ah[mi], &bh[ni >> 1][(ni & 1) * 2]);
            if (NOP == 2) {
                // order: al*bh next (so bh dies before bl loads) -> lower reg pressure
                uint32_t al[4][4];
                #pragma unroll
                for (int mi = 0; mi < 4; mi++) ldsm4(al[mi], bb + 1u * 8192u + offA[mi][ks]);
                #pragma unroll
                for (int mi = 0; mi < 4; mi++)
                    #pragma unroll
                    for (int ni = 0; ni < 4; ni++)
                        mma16816(acc[mi][ni], al[mi], &bh[ni >> 1][(ni & 1) * 2]);
                uint32_t bl[2][4];
                #pragma unroll
                for (int np = 0; np < 2; np++) ldsm4(bl[np], bb + 3u * 8192u + offB[np][ks]);
                #pragma unroll
                for (int mi = 0; mi < 4; mi++)
                    #pragma unroll
                    for (int ni = 0; ni < 4; ni++)
                        mma16816(acc[mi][ni], ah[mi], &bl[ni >> 1][(ni & 1) * 2]);
            }
        }

        // issue chunk kt+NS-1 into buffer of chunk kt-1 (freed by this iteration's barrier)
        if (kt + NS - 1 < nkt) {
            const int ldst = (stage + NS - 1) % NS;
            const int kc = (kt + NS - 1) * 32 + su * 8;
            const uint32_t db = sbase + (uint32_t)ldst * STAGE;
            #pragma unroll
            for (int t = 0; t < NT; t++) {
                cp16(db + t * 8192u + soff0, gsrc[t] + (size_t)(rb[t] + sr0) * K + kc);
                cp16(db + t * 8192u + soff1, gsrc[t] + (size_t)(rb[t] + sr1) * K + kc);
            }
        }
        CP_COMMIT();
        stage = (stage + 1 < NS) ? stage + 1 : 0;
    }

    // -------- epilogue --------
    const int lr = lane >> 2;
    const int lc = (lane & 3) << 1;

    #pragma unroll
    for (int mi = 0; mi < 4; mi++) {
        #pragma unroll
        for (int h = 0; h < 2; h++) {
            const int lrow = wm * 64 + mi * 16 + h * 8 + lr;
            const int grow = m0 + lrow;
            float part = 0.0f;
            float invr = 0.0f;
            if (EPI == 3) invr = 1.0f / rsum[grow];
            #pragma unroll
            for (int ni = 0; ni < 4; ni++) {
                float v0 = acc[mi][ni][h * 2 + 0];
                float v1 = acc[mi][ni][h * 2 + 1];
                const int gcol = n0 + wn * 32 + ni * 8 + lc;
                const size_t o = (size_t)grow * Ncols + gcol;
                if (EPI == 0) {
                    float y0 = fabsf(v0), y1 = fabsf(v1);
                    __nv_bfloat16 h0 = __float2bfloat16(y0), h1 = __float2bfloat16(y1);
                    __nv_bfloat16 l0 = __float2bfloat16(y0 - __bfloat162float(h0));
                    __nv_bfloat16 l1 = __float2bfloat16(y1 - __bfloat162float(h1));
                    *(__nv_bfloat162*)(Chi + o) = __halves2bfloat162(h0, h1);
                    *(__nv_bfloat162*)(Clo + o) = __halves2bfloat162(l0, l1);
                } else if (EPI == 1) {
                    // transposed scatter: Chi is [Ncols-major, NR] = v^T
                    Chi[(size_t)gcol * NR + grow]       = __float2bfloat16(fabsf(v0));
                    Chi[(size_t)(gcol + 1) * NR + grow] = __float2bfloat16(fabsf(v1));
                } else if (EPI == 2) {
                    float e0 = exp2_poly(v0 * scale);
                    float e1 = exp2_poly(v1 * scale);
                    part += e0 + e1;
                    *(__nv_bfloat162*)(Chi + o) =
                        __halves2bfloat162(__float2bfloat16(e0), __float2bfloat16(e1));
                } else {
                    *(float2*)(Cf + o) = make_float2(v0 * invr, v1 * invr);
                }
            }
            if (EPI == 2) {
                part += __shfl_xor_sync(0xffffffffu, part, 1);
                part += __shfl_xor_sync(0xffffffffu, part, 2);
                if ((lane & 3) == 0) red[lrow][wn] = part;
            }
        }
    }
    if (EPI == 2) {
        __syncthreads();
        if (tid < 128)
            atomicAdd(&rsum[m0 + tid],
                      red[tid][0] + red[tid][1] + red[tid][2] + red[tid][3]);
    }
}

// ---------------- launch ----------------
extern "C" void kernel_launch(void* const* d_in, const int* in_sizes, int n_in,
                              void* d_out, int out_size)
{
    (void)in_sizes; (void)n_in; (void)out_size;
    const float* x  = (const float*)d_in[0];
    const float* W[3] = {(const float*)d_in[1], (const float*)d_in[2], (const float*)d_in[3]};
    float* out = (float*)d_out;

    __nv_bfloat16 *xhi, *xlo, *wth0, *wtl0, *qhi, *qlo, *khi, *klo, *vt, *E;
    float* rs;
    cudaGetSymbolAddress((void**)&xhi, g_xhi);
    cudaGetSymbolAddress((void**)&xlo, g_xlo);
    cudaGetSymbolAddress((void**)&wth0, g_wth);
    cudaGetSymbolAddress((void**)&wtl0, g_wtl);
    cudaGetSymbolAddress((void**)&qhi, g_qhi);
    cudaGetSymbolAddress((void**)&qlo, g_qlo);
    cudaGetSymbolAddress((void**)&khi, g_khi);
    cudaGetSymbolAddress((void**)&klo, g_klo);
    cudaGetSymbolAddress((void**)&vt,  g_vt);
    cudaGetSymbolAddress((void**)&E,   g_E);
    cudaGetSymbolAddress((void**)&rs,  g_rowsum);

    const int SM2 = 3 * 4 * 8192;   // 96 KB (split kernels)
    const int SM1 = 3 * 2 * 8192;   // 48 KB (single)
    cudaFuncSetAttribute(mma_gemm<2, 0>, cudaFuncAttributeMaxDynamicSharedMemorySize, SM2);
    cudaFuncSetAttribute(mma_gemm<2, 1>, cudaFuncAttributeMaxDynamicSharedMemorySize, SM2);
    cudaFuncSetAttribute(mma_gemm<2, 2>, cudaFuncAttributeMaxDynamicSharedMemorySize, SM2);
    cudaFuncSetAttribute(mma_gemm<1, 3>, cudaFuncAttributeMaxDynamicSharedMemorySize, SM1);

    const float SC2 = 0.06375869843f;       // log2(e)/sqrt(512)

    // launch order chosen so the dot GEMM is launch #6 (ncu -s 5 -c 1 captures it)
    split_x_k<<<(NR * DD / 4) / 256, 256>>>((const float4*)x);                     // 1
    trans_split_w_k<<<dim3(16, 16, 3), dim3(32, 8)>>>(W[0], W[1], W[2]);           // 2

    dim3 blk(256);
    dim3 gQKV(DD / 128, NR / 128);
    mma_gemm<2, 0><<<gQKV, blk, SM2>>>(xhi, xlo, wth0, wtl0, DD, DD,
                                       qhi, qlo, nullptr, nullptr, 0.f);           // 3
    mma_gemm<2, 0><<<gQKV, blk, SM2>>>(xhi, xlo, wth0 + (size_t)DD * DD,
                                       wtl0 + (size_t)DD * DD, DD, DD,
                                       khi, klo, nullptr, nullptr, 0.f);           // 4
    // v: abs -> bf16, written TRANSPOSED directly (v^T), no separate transpose kernel
    mma_gemm<2, 1><<<gQKV, blk, SM2>>>(xhi, xlo, wth0 + (size_t)2 * DD * DD,
                                       wtl0 + (size_t)2 * DD * DD, DD, DD,
                                       vt, nullptr, nullptr, nullptr, 0.f);        // 5

    // E = exp(q k^T / sqrt(d)) (global-max pass dropped; see R1 analysis), rowsum
    mma_gemm<2, 2><<<dim3(NR / 128, NR / 128), blk, SM2>>>(qhi, qlo, khi, klo, NR, DD,
                                                           E, nullptr, nullptr, rs, SC2); // 6
    // out = (E v) / rowsum
    mma_gemm<1, 3><<<dim3(DD / 128, NR / 128), blk, SM1>>>(E, nullptr, vt, nullptr, DD, NR,
                                                           nullptr, nullptr, out, rs, 0.f); // 7
}

// round 7
// speedup vs baseline: 2.3048x; 2.3048x over previous
#include <cuda_runtime.h>
#include <cuda_fp16.h>
#include <stdint.h>
#include <math.h>

#define NR 8192
#define DD 512

// ---------------- scratch (__device__ globals; no allocs allowed) ----------------
__device__ __align__(128) __half g_xh[(size_t)NR * DD];
__device__ __align__(128) __half g_wt[3][(size_t)DD * DD];   // W^T fp16
__device__ __align__(128) __half g_q [(size_t)NR * DD];
__device__ __align__(128) __half g_k [(size_t)NR * DD];
__device__ __align__(128) __half g_vb[(size_t)NR * DD];
__device__ __align__(128) __half g_vt[(size_t)DD * NR];      // v^T
__device__ __align__(128) __half g_E [(size_t)NR * NR];      // 128 MB, stores E * 2^-16
__device__ float g_rowsum[NR];                               // also scaled by 2^-16

// ---------------- helpers (arch-generic PTX: ldmatrix + mma.sync + cp.async) ---------
__device__ __forceinline__ uint32_t smem_u32(const void* p) {
    uint32_t a;
    asm("{ .reg .u64 t; cvta.to.shared.u64 t, %1; cvt.u32.u64 %0, t; }" : "=r"(a) : "l"(p));
    return a;
}
__device__ __forceinline__ void ldsm4(uint32_t r[4], uint32_t a) {
    asm volatile("ldmatrix.sync.aligned.m8n8.x4.shared.b16 {%0,%1,%2,%3}, [%4];"
                 : "=r"(r[0]), "=r"(r[1]), "=r"(r[2]), "=r"(r[3]) : "r"(a));
}
__device__ __forceinline__ void mma16816(float d[4], const uint32_t a[4], const uint32_t b[2]) {
    asm volatile("mma.sync.aligned.m16n8k16.row.col.f32.f16.f16.f32 "
                 "{%0,%1,%2,%3}, {%4,%5,%6,%7}, {%8,%9}, {%0,%1,%2,%3};"
                 : "+f"(d[0]), "+f"(d[1]), "+f"(d[2]), "+f"(d[3])
                 : "r"(a[0]), "r"(a[1]), "r"(a[2]), "r"(a[3]), "r"(b[0]), "r"(b[1]));
}
__device__ __forceinline__ void cp16(uint32_t saddr, const void* gaddr) {
    asm volatile("cp.async.cg.shared.global [%0], [%1], 16;" :: "r"(saddr), "l"(gaddr));
}
#define CP_COMMIT() asm volatile("cp.async.commit_group;" ::: "memory")
#define CP_WAIT1()  asm volatile("cp.async.wait_group 1;" ::: "memory")

// 2^t for t in [-16, ~14] (biased); handles negative t via rintf + exponent bits.
__device__ __forceinline__ float exp2_poly(float t) {
    float fi = rintf(t);
    float f = t - fi;
    float p = 0.00015403530393381606f;
    p = fmaf(p, f, 0.0013333558146428443f);
    p = fmaf(p, f, 0.009618129107628477f);
    p = fmaf(p, f, 0.05550410866482158f);
    p = fmaf(p, f, 0.2402265069591007f);
    p = fmaf(p, f, 0.6931471805599453f);
    p = fmaf(p, f, 1.0f);
    return __int_as_float(((int)fi + 127) << 23) * p;
}

// ---------------- prep kernels ----------------
__global__ void conv_x_k(const float4* __restrict__ x) {
    size_t i = (size_t)blockIdx.x * 256 + threadIdx.x;
    if (i < NR) g_rowsum[i] = 0.0f;                 // fused rowsum zeroing
    float4 v = x[i];
    __half2* H = (__half2*)g_xh;
    H[2 * i]     = __floats2half2_rn(v.x, v.y);
    H[2 * i + 1] = __floats2half2_rn(v.z, v.w);
}

__global__ void trans_w_k(const float* __restrict__ W0, const float* __restrict__ W1,
                          const float* __restrict__ W2) {
    __shared__ float t[32][33];
    const float* W = (blockIdx.z == 0) ? W0 : (blockIdx.z == 1) ? W1 : W2;
    __half* T = g_wt[blockIdx.z];
    int tx = threadIdx.x, ty = threadIdx.y;
    int xi = blockIdx.x * 32 + tx, yi = blockIdx.y * 32 + ty;
    #pragma unroll
    for (int i = 0; i < 32; i += 8) t[ty + i][tx] = W[(size_t)(yi + i) * DD + xi];
    __syncthreads();
    int xo = blockIdx.y * 32 + tx, yo = blockIdx.x * 32 + ty;
    #pragma unroll
    for (int i = 0; i < 32; i += 8)
        T[(size_t)(yo + i) * DD + xo] = __float2half_rn(t[tx][ty + i]);
}

__global__ void trans_v_k() {
    __shared__ __half t[32][33];
    int tx = threadIdx.x, ty = threadIdx.y;
    int xi = blockIdx.x * 32 + tx, yi = blockIdx.y * 32 + ty;   // xi over DD, yi over NR
    #pragma unroll
    for (int i = 0; i < 32; i += 8) t[ty + i][tx] = g_vb[(size_t)(yi + i) * DD + xi];
    __syncthreads();
    int xo = blockIdx.y * 32 + tx, yo = blockIdx.x * 32 + ty;   // xo over NR, yo over DD
    #pragma unroll
    for (int i = 0; i < 32; i += 8) g_vt[(size_t)(yo + i) * NR + xo] = t[tx][ty + i];
}

// ============ mma.sync GEMM: D[M,Ncols] = A[M,K] x B[Ncols,K]^T, fp16 in, fp32 accum =====
// EPI 0: abs -> fp16 (Ch)
// EPI 2: exp2(acc*scale - 16) -> fp16 Ch + rowsum atomics   (2^-16 bias cancels in EPI 3)
// EPI 3: acc/rowsum -> f32 Cf
// Block 128x128, BK=32, 8 warps (2m x 4n), warp 64x32 (4x4 m16n8k16).
// cp.async 3-stage pipeline; smem 64B rows, swizzle unit' = unit^((row>>1)&3).
template<int EPI>
__global__ __launch_bounds__(256, 2)
void mma_gemm(const __half* __restrict__ A, const __half* __restrict__ B,
              int Ncols, int K,
              __half* __restrict__ Ch, float* __restrict__ Cf,
              float* __restrict__ rsum, float scale)
{
    constexpr int NS = 3;                        // pipeline stages
    constexpr uint32_t STAGE = 2u * 8192u;       // A tile + B tile
    extern __shared__ char dyn[];
    __shared__ float red[128][4];

    const int tid = threadIdx.x;
    const int lane = tid & 31, wid = tid >> 5;
    const int wm = wid & 1, wn = wid >> 1;
    const int m0 = blockIdx.y * 128, n0 = blockIdx.x * 128;
    const uint32_t sbase = smem_u32(dyn);

    const int su = tid & 3;
    const int sr0 = tid >> 2, sr1 = sr0 + 64;
    const uint32_t soff0 = sr0 * 64 + ((su ^ ((sr0 >> 1) & 3)) << 4);
    const uint32_t soff1 = sr1 * 64 + ((su ^ ((sr1 >> 1) & 3)) << 4);

    uint32_t offA[4][2], offB[2][2];
    {
        const int ra = lane & 15, ua = lane >> 4;
        #pragma unroll
        for (int mi = 0; mi < 4; mi++)
            #pragma unroll
            for (int ks = 0; ks < 2; ks++) {
                int r = wm * 64 + mi * 16 + ra;
                int u = ks * 2 + ua;
                offA[mi][ks] = r * 64 + ((u ^ ((r >> 1) & 3)) << 4);
            }
        const int rbv = ((lane >> 4) << 3) + (lane & 7), ub = (lane >> 3) & 1;
        #pragma unroll
        for (int np = 0; np < 2; np++)
            #pragma unroll
            for (int ks = 0; ks < 2; ks++) {
                int r = wn * 32 + np * 16 + rbv;
                int u = ks * 2 + ub;
                offB[np][ks] = r * 64 + ((u ^ ((r >> 1) & 3)) << 4) + 8192u;
            }
    }

    float acc[4][4][4];
    #pragma unroll
    for (int a = 0; a < 4; a++)
        #pragma unroll
        for (int b = 0; b < 4; b++)
            #pragma unroll
            for (int c = 0; c < 4; c++) acc[a][b][c] = 0.0f;

    const int nkt = K >> 5;

    // prologue: stage chunks 0, 1
    #pragma unroll
    for (int s = 0; s < NS - 1; s++) {
        const int kc = s * 32 + su * 8;
        const uint32_t db = sbase + (uint32_t)s * STAGE;
        cp16(db + soff0,         A + (size_t)(m0 + sr0) * K + kc);
        cp16(db + soff1,         A + (size_t)(m0 + sr1) * K + kc);
        cp16(db + 8192u + soff0, B + (size_t)(n0 + sr0) * K + kc);
        cp16(db + 8192u + soff1, B + (size_t)(n0 + sr1) * K + kc);
        CP_COMMIT();
    }

    int stage = 0;
    for (int kt = 0; kt < nkt; kt++) {
        // issue chunk kt+2 into the buffer freed at end of iteration kt-1
        if (kt + NS - 1 < nkt) {
            const int ldst = (stage + NS - 1) % NS;
            const int kc = (kt + NS - 1) * 32 + su * 8;
            const uint32_t db = sbase + (uint32_t)ldst * STAGE;
            cp16(db + soff0,         A + (size_t)(m0 + sr0) * K + kc);
            cp16(db + soff1,         A + (size_t)(m0 + sr1) * K + kc);
            cp16(db + 8192u + soff0, B + (size_t)(n0 + sr0) * K + kc);
            cp16(db + 8192u + soff1, B + (size_t)(n0 + sr1) * K + kc);
        }
        CP_COMMIT();
        CP_WAIT1();          // chunk kt resident
        __syncthreads();

        const uint32_t bb = sbase + (uint32_t)stage * STAGE;
        #pragma unroll
        for (int ks = 0; ks < 2; ks++) {
            uint32_t ah[4][4];
            #pragma unroll
            for (int mi = 0; mi < 4; mi++) ldsm4(ah[mi], bb + offA[mi][ks]);
            uint32_t bh[2][4];
            #pragma unroll
            for (int np = 0; np < 2; np++) ldsm4(bh[np], bb + offB[np][ks]);
            #pragma unroll
            for (int mi = 0; mi < 4; mi++)
                #pragma unroll
                for (int ni = 0; ni < 4; ni++)
                    mma16816(acc[mi][ni], ah[mi], &bh[ni >> 1][(ni & 1) * 2]);
        }
        __syncthreads();     // stage buffer free for next iteration's issue
        stage = (stage + 1 < NS) ? stage + 1 : 0;
    }

    // -------- epilogue --------
    const int lr = lane >> 2;
    const int lc = (lane & 3) << 1;

    #pragma unroll
    for (int mi = 0; mi < 4; mi++) {
        #pragma unroll
        for (int h = 0; h < 2; h++) {
            const int lrow = wm * 64 + mi * 16 + h * 8 + lr;
            const int grow = m0 + lrow;
            float part = 0.0f;
            float invr = 0.0f;
            if (EPI == 3) invr = 1.0f / rsum[grow];
            #pragma unroll
            for (int ni = 0; ni < 4; ni++) {
                float v0 = acc[mi][ni][h * 2 + 0];
                float v1 = acc[mi][ni][h * 2 + 1];
                const int gcol = n0 + wn * 32 + ni * 8 + lc;
                const size_t o = (size_t)grow * Ncols + gcol;
                if (EPI == 0) {
                    *(__half2*)(Ch + o) = __floats2half2_rn(fabsf(v0), fabsf(v1));
                } else if (EPI == 2) {
                    // E' = 2^(dot*scale - 16): fits fp16 (max dot*scale ~19 -> 2^3=8)
                    // the 2^-16 bias cancels exactly in EPI 3's division.
                    float e0 = exp2_poly(fmaf(v0, scale, -16.0f));
                    float e1 = exp2_poly(fmaf(v1, scale, -16.0f));
                    part += e0 + e1;
                    *(__half2*)(Ch + o) = __floats2half2_rn(e0, e1);
                } else {
                    *(float2*)(Cf + o) = make_float2(v0 * invr, v1 * invr);
                }
            }
            if (EPI == 2) {
                part += __shfl_xor_sync(0xffffffffu, part, 1);
                part += __shfl_xor_sync(0xffffffffu, part, 2);
                if ((lane & 3) == 0) red[lrow][wn] = part;
            }
        }
    }
    if (EPI == 2) {
        __syncthreads();
        if (tid < 128)
            atomicAdd(&rsum[m0 + tid],
                      red[tid][0] + red[tid][1] + red[tid][2] + red[tid][3]);
    }
}

// ---------------- launch ----------------
extern "C" void kernel_launch(void* const* d_in, const int* in_sizes, int n_in,
                              void* d_out, int out_size)
{
    (void)in_sizes; (void)n_in; (void)out_size;
    const float* x  = (const float*)d_in[0];
    const float* W[3] = {(const float*)d_in[1], (const float*)d_in[2], (const float*)d_in[3]};
    float* out = (float*)d_out;

    __half *xh, *wt0, *q, *k, *vb, *vt, *E;
    float* rs;
    cudaGetSymbolAddress((void**)&xh,  g_xh);
    cudaGetSymbolAddress((void**)&wt0, g_wt);
    cudaGetSymbolAddress((void**)&q,   g_q);
    cudaGetSymbolAddress((void**)&k,   g_k);
    cudaGetSymbolAddress((void**)&vb,  g_vb);
    cudaGetSymbolAddress((void**)&vt,  g_vt);
    cudaGetSymbolAddress((void**)&E,   g_E);
    cudaGetSymbolAddress((void**)&rs,  g_rowsum);

    const int SM = 3 * 2 * 8192;   // 48 KB
    cudaFuncSetAttribute(mma_gemm<0>, cudaFuncAttributeMaxDynamicSharedMemorySize, SM);
    cudaFuncSetAttribute(mma_gemm<2>, cudaFuncAttributeMaxDynamicSharedMemorySize, SM);
    cudaFuncSetAttribute(mma_gemm<3>, cudaFuncAttributeMaxDynamicSharedMemorySize, SM);

    const float SC2 = 0.06375869843f;       // log2(e)/sqrt(512)

    // launch order: dot GEMM is launch #6 (ncu -s 5 -c 1 captures it)
    conv_x_k<<<(NR * DD / 4) / 256, 256>>>((const float4*)x);                      // 1
    trans_w_k<<<dim3(16, 16, 3), dim3(32, 8)>>>(W[0], W[1], W[2]);                 // 2

    dim3 blk(256);
    dim3 gQKV(DD / 128, NR / 128);
    mma_gemm<0><<<gQKV, blk, SM>>>(xh, wt0, DD, DD, q, nullptr, nullptr, 0.f);     // 3
    mma_gemm<0><<<gQKV, blk, SM>>>(xh, wt0 + (size_t)DD * DD, DD, DD,
                                   k, nullptr, nullptr, 0.f);                      // 4
    mma_gemm<0><<<gQKV, blk, SM>>>(xh, wt0 + (size_t)2 * DD * DD, DD, DD,
                                   vb, nullptr, nullptr, 0.f);                     // 5

    // E' = exp(q k^T / sqrt(d)) * 2^-16 (global-max pass dropped; bias cancels), rowsum
    mma_gemm<2><<<dim3(NR / 128, NR / 128), blk, SM>>>(q, k, NR, DD,
                                                       E, nullptr, rs, SC2);       // 6
    trans_v_k<<<dim3(DD / 32, NR / 32), dim3(32, 8)>>>();                          // 7
    // out = (E' v) / rowsum'
    mma_gemm<3><<<dim3(DD / 128, NR / 128), blk, SM>>>(E, vt, DD, NR,
                                                       nullptr, out, rs, 0.f);     // 8
}

// round 8
// speedup vs baseline: 2.6948x; 1.1693x over previous
#include <cuda_runtime.h>
#include <cuda_fp16.h>
#include <stdint.h>
#include <math.h>

#define NR 8192
#define DD 512

// ---------------- scratch (__device__ globals; no allocs allowed) ----------------
__device__ __align__(128) __half g_xh[(size_t)NR * DD];
__device__ __align__(128) __half g_wt[3][(size_t)DD * DD];   // W^T fp16
__device__ __align__(128) __half g_q [(size_t)NR * DD];
__device__ __align__(128) __half g_k [(size_t)NR * DD];
__device__ __align__(128) __half g_vb[(size_t)NR * DD];
__device__ __align__(128) __half g_vt[(size_t)DD * NR];      // v^T
__device__ __align__(128) __half g_E [(size_t)NR * NR];      // 128 MB, stores E * 2^-16
__device__ float g_rowsum[NR];                               // also scaled by 2^-16

// ---------------- helpers (arch-generic PTX: ldmatrix + mma.sync + cp.async) ---------
__device__ __forceinline__ uint32_t smem_u32(const void* p) {
    uint32_t a;
    asm("{ .reg .u64 t; cvta.to.shared.u64 t, %1; cvt.u32.u64 %0, t; }" : "=r"(a) : "l"(p));
    return a;
}
__device__ __forceinline__ void ldsm4(uint32_t r[4], uint32_t a) {
    asm volatile("ldmatrix.sync.aligned.m8n8.x4.shared.b16 {%0,%1,%2,%3}, [%4];"
                 : "=r"(r[0]), "=r"(r[1]), "=r"(r[2]), "=r"(r[3]) : "r"(a));
}
__device__ __forceinline__ void mma16816(float d[4], const uint32_t a[4], const uint32_t b[2]) {
    asm volatile("mma.sync.aligned.m16n8k16.row.col.f32.f16.f16.f32 "
                 "{%0,%1,%2,%3}, {%4,%5,%6,%7}, {%8,%9}, {%0,%1,%2,%3};"
                 : "+f"(d[0]), "+f"(d[1]), "+f"(d[2]), "+f"(d[3])
                 : "r"(a[0]), "r"(a[1]), "r"(a[2]), "r"(a[3]), "r"(b[0]), "r"(b[1]));
}
__device__ __forceinline__ void cp16(uint32_t saddr, const void* gaddr) {
    asm volatile("cp.async.cg.shared.global [%0], [%1], 16;" :: "r"(saddr), "l"(gaddr));
}
#define CP_COMMIT() asm volatile("cp.async.commit_group;" ::: "memory")
#define CP_WAIT1()  asm volatile("cp.async.wait_group 1;" ::: "memory")

// 2^t for t in [-16, ~14]
__device__ __forceinline__ float exp2_poly(float t) {
    float fi = rintf(t);
    float f = t - fi;
    float p = 0.00015403530393381606f;
    p = fmaf(p, f, 0.0013333558146428443f);
    p = fmaf(p, f, 0.009618129107628477f);
    p = fmaf(p, f, 0.05550410866482158f);
    p = fmaf(p, f, 0.2402265069591007f);
    p = fmaf(p, f, 0.6931471805599453f);
    p = fmaf(p, f, 1.0f);
    return __int_as_float(((int)fi + 127) << 23) * p;
}

// ---------------- prep kernels ----------------
__global__ void conv_x_k(const float4* __restrict__ x) {
    size_t i = (size_t)blockIdx.x * 256 + threadIdx.x;
    if (i < NR) g_rowsum[i] = 0.0f;
    float4 v = x[i];
    __half2* H = (__half2*)g_xh;
    H[2 * i]     = __floats2half2_rn(v.x, v.y);
    H[2 * i + 1] = __floats2half2_rn(v.z, v.w);
}

__global__ void trans_w_k(const float* __restrict__ W0, const float* __restrict__ W1,
                          const float* __restrict__ W2) {
    __shared__ float t[32][33];
    const float* W = (blockIdx.z == 0) ? W0 : (blockIdx.z == 1) ? W1 : W2;
    __half* T = g_wt[blockIdx.z];
    int tx = threadIdx.x, ty = threadIdx.y;
    int xi = blockIdx.x * 32 + tx, yi = blockIdx.y * 32 + ty;
    #pragma unroll
    for (int i = 0; i < 32; i += 8) t[ty + i][tx] = W[(size_t)(yi + i) * DD + xi];
    __syncthreads();
    int xo = blockIdx.y * 32 + tx, yo = blockIdx.x * 32 + ty;
    #pragma unroll
    for (int i = 0; i < 32; i += 8)
        T[(size_t)(yo + i) * DD + xo] = __float2half_rn(t[tx][ty + i]);
}

__global__ void trans_v_k() {
    __shared__ __half t[32][33];
    int tx = threadIdx.x, ty = threadIdx.y;
    int xi = blockIdx.x * 32 + tx, yi = blockIdx.y * 32 + ty;
    #pragma unroll
    for (int i = 0; i < 32; i += 8) t[ty + i][tx] = g_vb[(size_t)(yi + i) * DD + xi];
    __syncthreads();
    int xo = blockIdx.y * 32 + tx, yo = blockIdx.x * 32 + ty;
    #pragma unroll
    for (int i = 0; i < 32; i += 8) g_vt[(size_t)(yo + i) * NR + xo] = t[tx][ty + i];
}

// ============ mma.sync GEMM: D[M,Ncols] = A[M,K] x B[Ncols,K]^T, fp16 in, fp32 accum =====
// EPI 0: abs -> fp16   EPI 2: exp2(acc*scale - 16) -> fp16 + rowsum   EPI 3: acc/rowsum -> f32
// Block 128x128, BK=64, 8 warps (2m x 4n), warp 64x32 (4x4 m16n8k16), cp.async 3-stage.
// smem tile: 128 rows x 128 B (64 halves); SW128 swizzle: unit ^= row&7.
// k-step addressing: off(ks) = off(0) ^ (ks<<5) (u-bits are carry-free).
template<int EPI>
__global__ __launch_bounds__(256, 2)
void mma_gemm(const __half* __restrict__ A, const __half* __restrict__ B,
              int Ncols, int K,
              __half* __restrict__ Ch, float* __restrict__ Cf,
              float* __restrict__ rsum, float scale)
{
    constexpr int NS = 3;                        // pipeline stages
    constexpr uint32_t TILE = 16384u;            // 128 x 128 B
    constexpr uint32_t STAGE = 2u * TILE;        // A tile + B tile
    extern __shared__ char dyn[];
    __shared__ float red[128][4];

    const int tid = threadIdx.x;
    const int lane = tid & 31, wid = tid >> 5;
    const int wm = wid & 1, wn = wid >> 1;
    const int m0 = blockIdx.y * 128, n0 = blockIdx.x * 128;
    const uint32_t sbase = smem_u32(dyn);

    // cp.async mapping: unit su (0..7), rows sr+32j (j=0..3); (sr+32j)&7 == sr&7
    const int su = tid & 7;
    const int sr = tid >> 3;                     // 0..31
    const uint32_t soff = sr * 128 + ((su ^ (sr & 7)) << 4);

    // ldmatrix per-lane byte offsets at ks=0
    uint32_t offA[4], offB[2];
    {
        const int ra = lane & 15, ua = lane >> 4;
        #pragma unroll
        for (int mi = 0; mi < 4; mi++) {
            int r = wm * 64 + mi * 16 + ra;
            offA[mi] = r * 128 + ((ua ^ (r & 7)) << 4);
        }
        const int rbv = ((lane >> 4) << 3) + (lane & 7), ub = (lane >> 3) & 1;
        #pragma unroll
        for (int np = 0; np < 2; np++) {
            int r = wn * 32 + np * 16 + rbv;
            offB[np] = TILE + r * 128 + ((ub ^ (r & 7)) << 4);
        }
    }

    float acc[4][4][4];
    #pragma unroll
    for (int a = 0; a < 4; a++)
        #pragma unroll
        for (int b = 0; b < 4; b++)
            #pragma unroll
            for (int c = 0; c < 4; c++) acc[a][b][c] = 0.0f;

    const int nkt = K >> 6;                      // chunks of 64

    // prologue: stage chunks 0, 1
    #pragma unroll
    for (int s = 0; s < NS - 1; s++) {
        const int kc = s * 64 + su * 8;
        const uint32_t db = sbase + (uint32_t)s * STAGE;
        #pragma unroll
        for (int j = 0; j < 4; j++) {
            cp16(db + soff + j * 4096u,        A + (size_t)(m0 + sr + 32 * j) * K + kc);
            cp16(db + TILE + soff + j * 4096u, B + (size_t)(n0 + sr + 32 * j) * K + kc);
        }
        CP_COMMIT();
    }

    int stage = 0;
    for (int kt = 0; kt < nkt; kt++) {
        // issue chunk kt+2 into the buffer freed at end of iteration kt-1
        if (kt + NS - 1 < nkt) {
            const int ldst = (stage + NS - 1) % NS;
            const int kc = (kt + NS - 1) * 64 + su * 8;
            const uint32_t db = sbase + (uint32_t)ldst * STAGE;
            #pragma unroll
            for (int j = 0; j < 4; j++) {
                cp16(db + soff + j * 4096u,        A + (size_t)(m0 + sr + 32 * j) * K + kc);
                cp16(db + TILE + soff + j * 4096u, B + (size_t)(n0 + sr + 32 * j) * K + kc);
            }
        }
        CP_COMMIT();
        CP_WAIT1();          // chunk kt resident
        __syncthreads();

        const uint32_t bb = sbase + (uint32_t)stage * STAGE;
        #pragma unroll
        for (int ks = 0; ks < 4; ks++) {
            const uint32_t kx = (uint32_t)ks << 5;
            uint32_t ah[4][4];
            #pragma unroll
            for (int mi = 0; mi < 4; mi++) ldsm4(ah[mi], bb + (offA[mi] ^ kx));
            uint32_t bh[2][4];
            #pragma unroll
            for (int np = 0; np < 2; np++) ldsm4(bh[np], bb + (offB[np] ^ kx));
            #pragma unroll
            for (int mi = 0; mi < 4; mi++)
                #pragma unroll
                for (int ni = 0; ni < 4; ni++)
                    mma16816(acc[mi][ni], ah[mi], &bh[ni >> 1][(ni & 1) * 2]);
        }
        __syncthreads();     // stage buffer free for next iteration's issue
        stage = (stage + 1 < NS) ? stage + 1 : 0;
    }

    // -------- epilogue --------
    const int lr = lane >> 2;
    const int lc = (lane & 3) << 1;

    #pragma unroll
    for (int mi = 0; mi < 4; mi++) {
        #pragma unroll
        for (int h = 0; h < 2; h++) {
            const int lrow = wm * 64 + mi * 16 + h * 8 + lr;
            const int grow = m0 + lrow;
            float part = 0.0f;
            float invr = 0.0f;
            if (EPI == 3) invr = 1.0f / rsum[grow];
            #pragma unroll
            for (int ni = 0; ni < 4; ni++) {
                float v0 = acc[mi][ni][h * 2 + 0];
                float v1 = acc[mi][ni][h * 2 + 1];
                const int gcol = n0 + wn * 32 + ni * 8 + lc;
                const size_t o = (size_t)grow * Ncols + gcol;
                if (EPI == 0) {
                    *(__half2*)(Ch + o) = __floats2half2_rn(fabsf(v0), fabsf(v1));
                } else if (EPI == 2) {
                    float e0 = exp2_poly(fmaf(v0, scale, -16.0f));
                    float e1 = exp2_poly(fmaf(v1, scale, -16.0f));
                    part += e0 + e1;
                    *(__half2*)(Ch + o) = __floats2half2_rn(e0, e1);
                } else {
                    *(float2*)(Cf + o) = make_float2(v0 * invr, v1 * invr);
                }
            }
            if (EPI == 2) {
                part += __shfl_xor_sync(0xffffffffu, part, 1);
                part += __shfl_xor_sync(0xffffffffu, part, 2);
                if ((lane & 3) == 0) red[lrow][wn] = part;
            }
        }
    }
    if (EPI == 2) {
        __syncthreads();
        if (tid < 128)
            atomicAdd(&rsum[m0 + tid],
                      red[tid][0] + red[tid][1] + red[tid][2] + red[tid][3]);
    }
}

// ---------------- launch ----------------
extern "C" void kernel_launch(void* const* d_in, const int* in_sizes, int n_in,
                              void* d_out, int out_size)
{
    (void)in_sizes; (void)n_in; (void)out_size;
    const float* x  = (const float*)d_in[0];
    const float* W[3] = {(const float*)d_in[1], (const float*)d_in[2], (const float*)d_in[3]};
    float* out = (float*)d_out;

    __half *xh, *wt0, *q, *k, *vb, *vt, *E;
    float* rs;
    cudaGetSymbolAddress((void**)&xh,  g_xh);
    cudaGetSymbolAddress((void**)&wt0, g_wt);
    cudaGetSymbolAddress((void**)&q,   g_q);
    cudaGetSymbolAddress((void**)&k,   g_k);
    cudaGetSymbolAddress((void**)&vb,  g_vb);
    cudaGetSymbolAddress((void**)&vt,  g_vt);
    cudaGetSymbolAddress((void**)&E,   g_E);
    cudaGetSymbolAddress((void**)&rs,  g_rowsum);

    const int SM = 3 * 2 * 16384;   // 96 KB
    cudaFuncSetAttribute(mma_gemm<0>, cudaFuncAttributeMaxDynamicSharedMemorySize, SM);
    cudaFuncSetAttribute(mma_gemm<2>, cudaFuncAttributeMaxDynamicSharedMemorySize, SM);
    cudaFuncSetAttribute(mma_gemm<3>, cudaFuncAttributeMaxDynamicSharedMemorySize, SM);

    const float SC2 = 0.06375869843f;       // log2(e)/sqrt(512)

    // launch order: dot GEMM is launch #6 (ncu -s 5 -c 1 captures it)
    conv_x_k<<<(NR * DD / 4) / 256, 256>>>((const float4*)x);                      // 1
    trans_w_k<<<dim3(16, 16, 3), dim3(32, 8)>>>(W[0], W[1], W[2]);                 // 2

    dim3 blk(256);
    dim3 gQKV(DD / 128, NR / 128);
    mma_gemm<0><<<gQKV, blk, SM>>>(xh, wt0, DD, DD, q, nullptr, nullptr, 0.f);     // 3
    mma_gemm<0><<<gQKV, blk, SM>>>(xh, wt0 + (size_t)DD * DD, DD, DD,
                                   k, nullptr, nullptr, 0.f);                      // 4
    mma_gemm<0><<<gQKV, blk, SM>>>(xh, wt0 + (size_t)2 * DD * DD, DD, DD,
                                   vb, nullptr, nullptr, 0.f);                     // 5

    // E' = exp(q k^T / sqrt(d)) * 2^-16 (bias cancels in the final divide), rowsum
    mma_gemm<2><<<dim3(NR / 128, NR / 128), blk, SM>>>(q, k, NR, DD,
                                                       E, nullptr, rs, SC2);       // 6
    trans_v_k<<<dim3(DD / 32, NR / 32), dim3(32, 8)>>>();                          // 7
    // out = (E' v) / rowsum'
    mma_gemm<3><<<dim3(DD / 128, NR / 128), blk, SM>>>(E, vt, DD, NR,
                                                       nullptr, out, rs, 0.f);     // 8
}

// round 9
// speedup vs baseline: 2.7876x; 1.0344x over previous
#include <cuda_runtime.h>
#include <cuda_fp16.h>
#include <stdint.h>
#include <math.h>

#define NR 8192
#define DD 512

// ---------------- scratch (__device__ globals; no allocs allowed) ----------------
__device__ __align__(128) __half g_xh[(size_t)NR * DD];
__device__ __align__(128) __half g_wt[3][(size_t)DD * DD];   // W^T fp16; rows concat = B[1536][512]
__device__ __align__(128) __half g_qk[(size_t)NR * 1024];    // q (cols 0-511) | k (cols 512-1023)
__device__ __align__(128) __half g_vb[(size_t)NR * DD];
__device__ __align__(128) __half g_vt[(size_t)DD * NR];      // v^T
__device__ __align__(128) __half g_E [(size_t)NR * NR];      // 128 MB, stores E * 2^-16
__device__ float g_rowsum[NR];                               // also scaled by 2^-16

// ---------------- helpers ----------------
__device__ __forceinline__ uint32_t smem_u32(const void* p) {
    uint32_t a;
    asm("{ .reg .u64 t; cvta.to.shared.u64 t, %1; cvt.u32.u64 %0, t; }" : "=r"(a) : "l"(p));
    return a;
}
__device__ __forceinline__ void ldsm4(uint32_t r[4], uint32_t a) {
    asm volatile("ldmatrix.sync.aligned.m8n8.x4.shared.b16 {%0,%1,%2,%3}, [%4];"
                 : "=r"(r[0]), "=r"(r[1]), "=r"(r[2]), "=r"(r[3]) : "r"(a));
}
__device__ __forceinline__ void mma16816(float d[4], const uint32_t a[4], const uint32_t b[2]) {
    asm volatile("mma.sync.aligned.m16n8k16.row.col.f32.f16.f16.f32 "
                 "{%0,%1,%2,%3}, {%4,%5,%6,%7}, {%8,%9}, {%0,%1,%2,%3};"
                 : "+f"(d[0]), "+f"(d[1]), "+f"(d[2]), "+f"(d[3])
                 : "r"(a[0]), "r"(a[1]), "r"(a[2]), "r"(a[3]), "r"(b[0]), "r"(b[1]));
}
__device__ __forceinline__ void cp16(uint32_t saddr, const void* gaddr) {
    asm volatile("cp.async.cg.shared.global [%0], [%1], 16;" :: "r"(saddr), "l"(gaddr));
}
#define CP_COMMIT() asm volatile("cp.async.commit_group;" ::: "memory")
#define CP_WAIT1()  asm volatile("cp.async.wait_group 1;" ::: "memory")

// 2^t for t in [-16, ~14]
__device__ __forceinline__ float exp2_poly(float t) {
    float fi = rintf(t);
    float f = t - fi;
    float p = 0.00015403530393381606f;
    p = fmaf(p, f, 0.0013333558146428443f);
    p = fmaf(p, f, 0.009618129107628477f);
    p = fmaf(p, f, 0.05550410866482158f);
    p = fmaf(p, f, 0.2402265069591007f);
    p = fmaf(p, f, 0.6931471805599453f);
    p = fmaf(p, f, 1.0f);
    return __int_as_float(((int)fi + 127) << 23) * p;
}

// ---------------- prep kernels ----------------
__global__ void conv_x_k(const float4* __restrict__ x) {
    size_t i = (size_t)blockIdx.x * 256 + threadIdx.x;
    if (i < NR) g_rowsum[i] = 0.0f;
    float4 v = x[i];
    __half2* H = (__half2*)g_xh;
    H[2 * i]     = __floats2half2_rn(v.x, v.y);
    H[2 * i + 1] = __floats2half2_rn(v.z, v.w);
}

__global__ void trans_w_k(const float* __restrict__ W0, const float* __restrict__ W1,
                          const float* __restrict__ W2) {
    __shared__ float t[32][33];
    const float* W = (blockIdx.z == 0) ? W0 : (blockIdx.z == 1) ? W1 : W2;
    __half* T = g_wt[blockIdx.z];
    int tx = threadIdx.x, ty = threadIdx.y;
    int xi = blockIdx.x * 32 + tx, yi = blockIdx.y * 32 + ty;
    #pragma unroll
    for (int i = 0; i < 32; i += 8) t[ty + i][tx] = W[(size_t)(yi + i) * DD + xi];
    __syncthreads();
    int xo = blockIdx.y * 32 + tx, yo = blockIdx.x * 32 + ty;
    #pragma unroll
    for (int i = 0; i < 32; i += 8)
        T[(size_t)(yo + i) * DD + xo] = __float2half_rn(t[tx][ty + i]);
}

__global__ void trans_v_k() {
    __shared__ __half t[32][33];
    int tx = threadIdx.x, ty = threadIdx.y;
    int xi = blockIdx.x * 32 + tx, yi = blockIdx.y * 32 + ty;
    #pragma unroll
    for (int i = 0; i < 32; i += 8) t[ty + i][tx] = g_vb[(size_t)(yi + i) * DD + xi];
    __syncthreads();
    int xo = blockIdx.y * 32 + tx, yo = blockIdx.x * 32 + ty;
    #pragma unroll
    for (int i = 0; i < 32; i += 8) g_vt[(size_t)(yo + i) * NR + xo] = t[tx][ty + i];
}

// ============ mma.sync GEMM: D[M,*] = A[M,K](lda) x B[*,K](ldb)^T, fp16 in, fp32 accum ====
// EPI 0 (merged qkv): abs -> fp16; gcol<1024 -> Ch[grow*1024+gcol] (q|k), else Ch2[grow*512+gcol-1024] (v)
// EPI 2 (dot):  exp2(acc*scale - 16) -> fp16 Ch (ldc) + rowsum atomics
// EPI 3 (E*v):  acc/rowsum -> f32 Cf (ldc)
// Block 128x128, BK=64, 8 warps (2m x 4n), warp 64x32 (4x4 m16n8k16), cp.async 3-stage.
// smem tile: 128 rows x 128 B; SW128 swizzle unit ^= row&7; k-step: off ^ (ks<<5).
// Single barrier per chunk: wait -> sync -> compute -> issue -> commit.
template<int EPI>
__global__ __launch_bounds__(256, 2)
void mma_gemm(const __half* __restrict__ A, int lda,
              const __half* __restrict__ B, int ldb,
              int K, int ldc,
              __half* __restrict__ Ch, __half* __restrict__ Ch2,
              float* __restrict__ Cf, float* __restrict__ rsum, float scale)
{
    constexpr int NS = 3;
    constexpr uint32_t TILE = 16384u;            // 128 x 128 B
    constexpr uint32_t STAGE = 2u * TILE;
    extern __shared__ char dyn[];
    __shared__ float red[128][4];

    const int tid = threadIdx.x;
    const int lane = tid & 31, wid = tid >> 5;
    const int wm = wid & 1, wn = wid >> 1;
    const int m0 = blockIdx.y * 128, n0 = blockIdx.x * 128;
    const uint32_t sbase = smem_u32(dyn);

    const int su = tid & 7;
    const int sr = tid >> 3;                     // 0..31
    const uint32_t soff = sr * 128 + ((su ^ (sr & 7)) << 4);

    uint32_t offA[4], offB[2];
    {
        const int ra = lane & 15, ua = lane >> 4;
        #pragma unroll
        for (int mi = 0; mi < 4; mi++) {
            int r = wm * 64 + mi * 16 + ra;
            offA[mi] = r * 128 + ((ua ^ (r & 7)) << 4);
        }
        const int rbv = ((lane >> 4) << 3) + (lane & 7), ub = (lane >> 3) & 1;
        #pragma unroll
        for (int np = 0; np < 2; np++) {
            int r = wn * 32 + np * 16 + rbv;
            offB[np] = TILE + r * 128 + ((ub ^ (r & 7)) << 4);
        }
    }

    float acc[4][4][4];
    #pragma unroll
    for (int a = 0; a < 4; a++)
        #pragma unroll
        for (int b = 0; b < 4; b++)
            #pragma unroll
            for (int c = 0; c < 4; c++) acc[a][b][c] = 0.0f;

    const int nkt = K >> 6;

    // prologue: stage chunks 0, 1
    #pragma unroll
    for (int s = 0; s < NS - 1; s++) {
        const int kc = s * 64 + su * 8;
        const uint32_t db = sbase + (uint32_t)s * STAGE;
        #pragma unroll
        for (int j = 0; j < 4; j++) {
            cp16(db + soff + j * 4096u,        A + (size_t)(m0 + sr + 32 * j) * lda + kc);
            cp16(db + TILE + soff + j * 4096u, B + (size_t)(n0 + sr + 32 * j) * ldb + kc);
        }
        CP_COMMIT();
    }

    int stage = 0;
    for (int kt = 0; kt < nkt; kt++) {
        CP_WAIT1();          // chunk kt resident
        __syncthreads();     // single barrier: all warps done reading buffer (kt-1)%NS

        const uint32_t bb = sbase + (uint32_t)stage * STAGE;
        #pragma unroll
        for (int ks = 0; ks < 4; ks++) {
            const uint32_t kx = (uint32_t)ks << 5;
            uint32_t ah[4][4];
            #pragma unroll
            for (int mi = 0; mi < 4; mi++) ldsm4(ah[mi], bb + (offA[mi] ^ kx));
            uint32_t bh[2][4];
            #pragma unroll
            for (int np = 0; np < 2; np++) ldsm4(bh[np], bb + (offB[np] ^ kx));
            #pragma unroll
            for (int mi = 0; mi < 4; mi++)
                #pragma unroll
                for (int ni = 0; ni < 4; ni++)
                    mma16816(acc[mi][ni], ah[mi], &bh[ni >> 1][(ni & 1) * 2]);
        }

        // issue chunk kt+2 into buffer (kt+2)%NS == (kt-1)%NS — safe post-barrier
        if (kt + NS - 1 < nkt) {
            const int ldst = (stage + NS - 1) % NS;
            const int kc = (kt + NS - 1) * 64 + su * 8;
            const uint32_t db = sbase + (uint32_t)ldst * STAGE;
            #pragma unroll
            for (int j = 0; j < 4; j++) {
                cp16(db + soff + j * 4096u,        A + (size_t)(m0 + sr + 32 * j) * lda + kc);
                cp16(db + TILE + soff + j * 4096u, B + (size_t)(n0 + sr + 32 * j) * ldb + kc);
            }
        }
        CP_COMMIT();         // unconditional: keeps wait_group accounting uniform
        stage = (stage + 1 < NS) ? stage + 1 : 0;
    }

    // -------- epilogue --------
    const int lr = lane >> 2;
    const int lc = (lane & 3) << 1;

    #pragma unroll
    for (int mi = 0; mi < 4; mi++) {
        #pragma unroll
        for (int h = 0; h < 2; h++) {
            const int lrow = wm * 64 + mi * 16 + h * 8 + lr;
            const int grow = m0 + lrow;
            float part = 0.0f;
            float invr = 0.0f;
            if (EPI == 3) invr = 1.0f / rsum[grow];
            #pragma unroll
            for (int ni = 0; ni < 4; ni++) {
                float v0 = acc[mi][ni][h * 2 + 0];
                float v1 = acc[mi][ni][h * 2 + 1];
                const int gcol = n0 + wn * 32 + ni * 8 + lc;
                if (EPI == 0) {
                    __half2 hv = __floats2half2_rn(fabsf(v0), fabsf(v1));
                    if (gcol < 1024)
                        *(__half2*)(Ch + (size_t)grow * 1024 + gcol) = hv;          // q|k
                    else
                        *(__half2*)(Ch2 + (size_t)grow * DD + (gcol - 1024)) = hv;  // v
                } else if (EPI == 2) {
                    float e0 = exp2_poly(fmaf(v0, scale, -16.0f));
                    float e1 = exp2_poly(fmaf(v1, scale, -16.0f));
                    part += e0 + e1;
                    *(__half2*)(Ch + (size_t)grow * ldc + gcol) = __floats2half2_rn(e0, e1);
                } else {
                    *(float2*)(Cf + (size_t)grow * ldc + gcol) = make_float2(v0 * invr, v1 * invr);
                }
            }
            if (EPI == 2) {
                part += __shfl_xor_sync(0xffffffffu, part, 1);
                part += __shfl_xor_sync(0xffffffffu, part, 2);
                if ((lane & 3) == 0) red[lrow][wn] = part;
            }
        }
    }
    if (EPI == 2) {
        __syncthreads();
        if (tid < 128)
            atomicAdd(&rsum[m0 + tid],
                      red[tid][0] + red[tid][1] + red[tid][2] + red[tid][3]);
    }
}

// ---------------- launch ----------------
extern "C" void kernel_launch(void* const* d_in, const int* in_sizes, int n_in,
                              void* d_out, int out_size)
{
    (void)in_sizes; (void)n_in; (void)out_size;
    const float* x  = (const float*)d_in[0];
    const float* W[3] = {(const float*)d_in[1], (const float*)d_in[2], (const float*)d_in[3]};
    float* out = (float*)d_out;

    __half *xh, *wt0, *qk, *vb, *vt, *E;
    float* rs;
    cudaGetSymbolAddress((void**)&xh,  g_xh);
    cudaGetSymbolAddress((void**)&wt0, g_wt);
    cudaGetSymbolAddress((void**)&qk,  g_qk);
    cudaGetSymbolAddress((void**)&vb,  g_vb);
    cudaGetSymbolAddress((void**)&vt,  g_vt);
    cudaGetSymbolAddress((void**)&E,   g_E);
    cudaGetSymbolAddress((void**)&rs,  g_rowsum);

    const int SM = 3 * 2 * 16384;   // 96 KB
    cudaFuncSetAttribute(mma_gemm<0>, cudaFuncAttributeMaxDynamicSharedMemorySize, SM);
    cudaFuncSetAttribute(mma_gemm<2>, cudaFuncAttributeMaxDynamicSharedMemorySize, SM);
    cudaFuncSetAttribute(mma_gemm<3>, cudaFuncAttributeMaxDynamicSharedMemorySize, SM);

    const float SC2 = 0.06375869843f;       // log2(e)/sqrt(512)
    dim3 blk(256);

    conv_x_k<<<(NR * DD / 4) / 256, 256>>>((const float4*)x);                       // 1
    trans_w_k<<<dim3(16, 16, 3), dim3(32, 8)>>>(W[0], W[1], W[2]);                  // 2

    // merged qkv: C[8192][1536] = |x @ [Wq|Wk|Wv]^T|, q|k -> g_qk, v -> g_vb
    mma_gemm<0><<<dim3(1536 / 128, NR / 128), blk, SM>>>(xh, DD, wt0, DD, DD, 0,
                                                         qk, vb, nullptr, nullptr, 0.f); // 3
    trans_v_k<<<dim3(DD / 32, NR / 32), dim3(32, 8)>>>();                           // 4

    // E' = exp(q k^T / sqrt(d)) * 2^-16 (bias cancels in the final divide), rowsum
    mma_gemm<2><<<dim3(NR / 128, NR / 128), blk, SM>>>(qk, 1024, qk + 512, 1024, DD, NR,
                                                       E, nullptr, nullptr, rs, SC2);    // 5
    // out = (E' v) / rowsum'   (ncu -s 5 -c 1 captures this launch)
    mma_gemm<3><<<dim3(DD / 128, NR / 128), blk, SM>>>(E, NR, vt, NR, NR, DD,
                                                       nullptr, nullptr, out, rs, 0.f);  // 6
}

// round 12
// speedup vs baseline: 2.7914x; 1.0014x over previous
#include <cuda_runtime.h>
#include <cuda_fp16.h>
#include <stdint.h>
#include <math.h>

#define NR 8192
#define DD 512

// ---------------- scratch (__device__ globals; no allocs allowed) ----------------
__device__ __align__(128) __half g_xh[(size_t)NR * DD];
__device__ __align__(128) __half g_wt[3][(size_t)DD * DD];   // W^T fp16; rows concat = B[1536][512]
__device__ __align__(128) __half g_qk[(size_t)NR * 1024];    // q (cols 0-511) | k (cols 512-1023)
__device__ __align__(128) __half g_vt[(size_t)DD * NR];      // v^T (written directly by qkv epi)
__device__ __align__(128) __half g_E [(size_t)NR * NR];      // 128 MB, stores E * 2^-16
__device__ float g_rowsum[NR];                               // also scaled by 2^-16

// ---------------- helpers ----------------
__device__ __forceinline__ uint32_t smem_u32(const void* p) {
    uint32_t a;
    asm("{ .reg .u64 t; cvta.to.shared.u64 t, %1; cvt.u32.u64 %0, t; }" : "=r"(a) : "l"(p));
    return a;
}
__device__ __forceinline__ void ldsm4(uint32_t r[4], uint32_t a) {
    asm volatile("ldmatrix.sync.aligned.m8n8.x4.shared.b16 {%0,%1,%2,%3}, [%4];"
                 : "=r"(r[0]), "=r"(r[1]), "=r"(r[2]), "=r"(r[3]) : "r"(a));
}
__device__ __forceinline__ void mma16816(float d[4], const uint32_t a[4], const uint32_t b[2]) {
    asm volatile("mma.sync.aligned.m16n8k16.row.col.f32.f16.f16.f32 "
                 "{%0,%1,%2,%3}, {%4,%5,%6,%7}, {%8,%9}, {%0,%1,%2,%3};"
                 : "+f"(d[0]), "+f"(d[1]), "+f"(d[2]), "+f"(d[3])
                 : "r"(a[0]), "r"(a[1]), "r"(a[2]), "r"(a[3]), "r"(b[0]), "r"(b[1]));
}
__device__ __forceinline__ void cp16(uint32_t saddr, const void* gaddr) {
    asm volatile("cp.async.cg.shared.global [%0], [%1], 16;" :: "r"(saddr), "l"(gaddr));
}
#define CP_COMMIT() asm volatile("cp.async.commit_group;" ::: "memory")
#define CP_WAIT1()  asm volatile("cp.async.wait_group 1;" ::: "memory")

// 2^t, t in [-16.5, ~14], magic-number split + deg-4 poly.
// err ~4e-5 rel (<< fp16 storage rounding 4.9e-4).
__device__ __forceinline__ float exp2_fast(float t) {
    const float MAGIC = 12582912.0f;             // 2^23 + 2^22
    float r = t + MAGIC;                         // rounds t to nearest int in mantissa
    float f = t - (r - MAGIC);                   // f in [-0.5, 0.5]
    float p = 0.009618129f;
    p = fmaf(p, f, 0.05550411f);
    p = fmaf(p, f, 0.2402265f);
    p = fmaf(p, f, 0.6931472f);
    p = fmaf(p, f, 1.0f);
    // r_bits = 0x4B400000 + i  ->  2^i bits = (r_bits + (127 - 0x4B400000)) << 23
    float es = __int_as_float((int)((__float_as_int(r) + 0xB4C0007Fu) << 23));
    return es * p;
}

// ---------------- prep kernels ----------------
__global__ void conv_x_k(const float4* __restrict__ x) {
    size_t i = (size_t)blockIdx.x * 256 + threadIdx.x;
    if (i < NR) g_rowsum[i] = 0.0f;
    float4 v = x[i];
    __half2* H = (__half2*)g_xh;
    H[2 * i]     = __floats2half2_rn(v.x, v.y);
    H[2 * i + 1] = __floats2half2_rn(v.z, v.w);
}

__global__ void trans_w_k(const float* __restrict__ W0, const float* __restrict__ W1,
                          const float* __restrict__ W2) {
    __shared__ float t[32][33];
    const float* W = (blockIdx.z == 0) ? W0 : (blockIdx.z == 1) ? W1 : W2;
    __half* T = g_wt[blockIdx.z];
    int tx = threadIdx.x, ty = threadIdx.y;
    int xi = blockIdx.x * 32 + tx, yi = blockIdx.y * 32 + ty;
    #pragma unroll
    for (int i = 0; i < 32; i += 8) t[ty + i][tx] = W[(size_t)(yi + i) * DD + xi];
    __syncthreads();
    int xo = blockIdx.y * 32 + tx, yo = blockIdx.x * 32 + ty;
    #pragma unroll
    for (int i = 0; i < 32; i += 8)
        T[(size_t)(yo + i) * DD + xo] = __float2half_rn(t[tx][ty + i]);
}

// ============ mma.sync GEMM: D[M,*] = A[M,K](lda) x B[*,K](ldb)^T, fp16 in, fp32 accum ====
// EPI 0 (merged qkv): abs -> fp16; gcol<1024 -> Ch[grow*1024+gcol] (q|k);
//                     gcol>=1024 -> transposed scatter Ch2[(gcol-1024)*NR + grow] (v^T)
// EPI 2 (dot):  exp2(acc*scale - 16) -> fp16 Ch (ldc) + rowsum atomics
// EPI 3 (E*v):  acc/rowsum -> f32 Cf (ldc)
// Block 128x128, BK=64, 8 warps (2m x 4n), warp 64x32 (4x4 m16n8k16), cp.async 3-stage.
// smem tile: 128 rows x 128 B; SW128 swizzle unit ^= row&7; k-step: off ^ (ks<<5).
// Single barrier per chunk: wait -> sync -> compute -> issue -> commit.
template<int EPI>
__global__ __launch_bounds__(256, 2)
void mma_gemm(const __half* __restrict__ A, int lda,
              const __half* __restrict__ B, int ldb,
              int K, int ldc,
              __half* __restrict__ Ch, __half* __restrict__ Ch2,
              float* __restrict__ Cf, float* __restrict__ rsum, float scale)
{
    constexpr int NS = 3;
    constexpr uint32_t TILE = 16384u;            // 128 x 128 B
    constexpr uint32_t STAGE = 2u * TILE;
    extern __shared__ char dyn[];
    __shared__ float red[128][4];

    const int tid = threadIdx.x;
    const int lane = tid & 31, wid = tid >> 5;
    const int wm = wid & 1, wn = wid >> 1;
    const int m0 = blockIdx.y * 128, n0 = blockIdx.x * 128;
    const uint32_t sbase = smem_u32(dyn);

    const int su = tid & 7;
    const int sr = tid >> 3;                     // 0..31
    const uint32_t soff = sr * 128 + ((su ^ (sr & 7)) << 4);

    uint32_t offA[4], offB[2];
    {
        const int ra = lane & 15, ua = lane >> 4;
        #pragma unroll
        for (int mi = 0; mi < 4; mi++) {
            int r = wm * 64 + mi * 16 + ra;
            offA[mi] = r * 128 + ((ua ^ (r & 7)) << 4);
        }
        const int rbv = ((lane >> 4) << 3) + (lane & 7), ub = (lane >> 3) & 1;
        #pragma unroll
        for (int np = 0; np < 2; np++) {
            int r = wn * 32 + np * 16 + rbv;
            offB[np] = TILE + r * 128 + ((ub ^ (r & 7)) << 4);
        }
    }

    float acc[4][4][4];
    #pragma unroll
    for (int a = 0; a < 4; a++)
        #pragma unroll
        for (int b = 0; b < 4; b++)
            #pragma unroll
            for (int c = 0; c < 4; c++) acc[a][b][c] = 0.0f;

    const int nkt = K >> 6;

    // prologue: stage chunks 0, 1
    #pragma unroll
    for (int s = 0; s < NS - 1; s++) {
        const int kc = s * 64 + su * 8;
        const uint32_t db = sbase + (uint32_t)s * STAGE;
        #pragma unroll
        for (int j = 0; j < 4; j++) {
            cp16(db + soff + j * 4096u,        A + (size_t)(m0 + sr + 32 * j) * lda + kc);
            cp16(db + TILE + soff + j * 4096u, B + (size_t)(n0 + sr + 32 * j) * ldb + kc);
        }
        CP_COMMIT();
    }

    int stage = 0;
    for (int kt = 0; kt < nkt; kt++) {
        CP_WAIT1();          // chunk kt resident
        __syncthreads();     // single barrier: all warps done reading buffer (kt-1)%NS

        const uint32_t bb = sbase + (uint32_t)stage * STAGE;
        #pragma unroll
        for (int ks = 0; ks < 4; ks++) {
            const uint32_t kx = (uint32_t)ks << 5;
            uint32_t ah[4][4];
            #pragma unroll
            for (int mi = 0; mi < 4; mi++) ldsm4(ah[mi], bb + (offA[mi] ^ kx));
            uint32_t bh[2][4];
            #pragma unroll
            for (int np = 0; np < 2; np++) ldsm4(bh[np], bb + (offB[np] ^ kx));
            #pragma unroll
            for (int mi = 0; mi < 4; mi++)
                #pragma unroll
                for (int ni = 0; ni < 4; ni++)
                    mma16816(acc[mi][ni], ah[mi], &bh[ni >> 1][(ni & 1) * 2]);
        }

        // issue chunk kt+2 into buffer (kt+2)%NS == (kt-1)%NS — safe post-barrier
        if (kt + NS - 1 < nkt) {
            const int ldst = (stage + NS - 1) % NS;
            const int kc = (kt + NS - 1) * 64 + su * 8;
            const uint32_t db = sbase + (uint32_t)ldst * STAGE;
            #pragma unroll
            for (int j = 0; j < 4; j++) {
                cp16(db + soff + j * 4096u,        A + (size_t)(m0 + sr + 32 * j) * lda + kc);
                cp16(db + TILE + soff + j * 4096u, B + (size_t)(n0 + sr + 32 * j) * ldb + kc);
            }
        }
        CP_COMMIT();         // unconditional: keeps wait_group accounting uniform
        stage = (stage + 1 < NS) ? stage + 1 : 0;
    }

    // -------- epilogue --------
    const int lr = lane >> 2;
    const int lc = (lane & 3) << 1;

    #pragma unroll
    for (int mi = 0; mi < 4; mi++) {
        #pragma unroll
        for (int h = 0; h < 2; h++) {
            const int lrow = wm * 64 + mi * 16 + h * 8 + lr;
            const int grow = m0 + lrow;
            float part = 0.0f;
            float invr = 0.0f;
            if (EPI == 3) invr = 1.0f / rsum[grow];
            #pragma unroll
            for (int ni = 0; ni < 4; ni++) {
                float v0 = acc[mi][ni][h * 2 + 0];
                float v1 = acc[mi][ni][h * 2 + 1];
                const int gcol = n0 + wn * 32 + ni * 8 + lc;
                if (EPI == 0) {
                    if (gcol < 1024) {
                        *(__half2*)(Ch + (size_t)grow * 1024 + gcol) =
                            __floats2half2_rn(fabsf(v0), fabsf(v1));      // q|k
                    } else {
                        // v^T: transposed scatter (column-major store)
                        Ch2[(size_t)(gcol - 1024) * NR + grow] = __float2half_rn(fabsf(v0));
                        Ch2[(size_t)(gcol - 1023) * NR + grow] = __float2half_rn(fabsf(v1));
                    }
                } else if (EPI == 2) {
                    float e0 = exp2_fast(fmaf(v0, scale, -16.0f));
                    float e1 = exp2_fast(fmaf(v1, scale, -16.0f));
                    part += e0 + e1;
                    *(__half2*)(Ch + (size_t)grow * ldc + gcol) = __floats2half2_rn(e0, e1);
                } else {
                    *(float2*)(Cf + (size_t)grow * ldc + gcol) = make_float2(v0 * invr, v1 * invr);
                }
            }
            if (EPI == 2) {
                part += __shfl_xor_sync(0xffffffffu, part, 1);
                part += __shfl_xor_sync(0xffffffffu, part, 2);
                if ((lane & 3) == 0) red[lrow][wn] = part;
            }
        }
    }
    if (EPI == 2) {
        __syncthreads();
        if (tid < 128)
            atomicAdd(&rsum[m0 + tid],
                      red[tid][0] + red[tid][1] + red[tid][2] + red[tid][3]);
    }
}

// ---------------- launch ----------------
extern "C" void kernel_launch(void* const* d_in, const int* in_sizes, int n_in,
                              void* d_out, int out_size)
{
    (void)in_sizes; (void)n_in; (void)out_size;
    const float* x  = (const float*)d_in[0];
    const float* W[3] = {(const float*)d_in[1], (const float*)d_in[2], (const float*)d_in[3]};
    float* out = (float*)d_out;

    __half *xh, *wt0, *qk, *vt, *E;
    float* rs;
    cudaGetSymbolAddress((void**)&xh,  g_xh);
    cudaGetSymbolAddress((void**)&wt0, g_wt);
    cudaGetSymbolAddress((void**)&qk,  g_qk);
    cudaGetSymbolAddress((void**)&vt,  g_vt);
    cudaGetSymbolAddress((void**)&E,   g_E);
    cudaGetSymbolAddress((void**)&rs,  g_rowsum);

    const int SM = 3 * 2 * 16384;   // 96 KB
    cudaFuncSetAttribute(mma_gemm<0>, cudaFuncAttributeMaxDynamicSharedMemorySize, SM);
    cudaFuncSetAttribute(mma_gemm<2>, cudaFuncAttributeMaxDynamicSharedMemorySize, SM);
    cudaFuncSetAttribute(mma_gemm<3>, cudaFuncAttributeMaxDynamicSharedMemorySize, SM);

    const float SC2 = 0.06375869843f;       // log2(e)/sqrt(512)
    dim3 blk(256);

    conv_x_k<<<(NR * DD / 4) / 256, 256>>>((const float4*)x);                       // 1
    trans_w_k<<<dim3(16, 16, 3), dim3(32, 8)>>>(W[0], W[1], W[2]);                  // 2

    // merged qkv: C[8192][1536] = |x @ [Wq|Wk|Wv]^T|; q|k -> g_qk, v -> g_vt (transposed)
    mma_gemm<0><<<dim3(1536 / 128, NR / 128), blk, SM>>>(xh, DD, wt0, DD, DD, 0,
                                                         qk, vt, nullptr, nullptr, 0.f); // 3

    // E' = exp(q k^T / sqrt(d)) * 2^-16 (bias cancels in the final divide), rowsum
    mma_gemm<2><<<dim3(NR / 128, NR / 128), blk, SM>>>(qk, 1024, qk + 512, 1024, DD, NR,
                                                       E, nullptr, nullptr, rs, SC2);    // 4
    // out = (E' v) / rowsum'
    mma_gemm<3><<<dim3(DD / 128, NR / 128), blk, SM>>>(E, NR, vt, NR, NR, DD,
                                                       nullptr, nullptr, out, rs, 0.f);  // 5
}